// round 6
// baseline (speedup 1.0000x reference)
#include <cuda_runtime.h>
#include <cuda_bf16.h>
#include <cstdint>

#define DM   768
#define NH   12
#define HD   64
#define B_   2
#define S_   2048
#define MTOT 4096
#define BH   (B_*NH)

// ---------------- scratch (__device__ globals) ------------------------------
__device__ __nv_bfloat16 g_Qh[BH * S_ * HD];
__device__ __nv_bfloat16 g_Ql[BH * S_ * HD];
__device__ __nv_bfloat16 g_Kh[BH * S_ * HD];
__device__ __nv_bfloat16 g_Kl[BH * S_ * HD];
__device__ __nv_bfloat16 g_Vh[BH * S_ * HD];
__device__ __nv_bfloat16 g_Vl[BH * S_ * HD];
__device__ __nv_bfloat16 g_xh[MTOT * DM];
__device__ __nv_bfloat16 g_xl[MTOT * DM];
__device__ __nv_bfloat16 g_Ch[MTOT * DM];
__device__ __nv_bfloat16 g_Cl[MTOT * DM];
__device__ __nv_bfloat16 g_Wth[4 * DM * DM];   // [N,K] hi
__device__ __nv_bfloat16 g_Wtl[4 * DM * DM];   // [N,K] lo

// ---------------- helpers ---------------------------------------------------
__device__ __forceinline__ uint32_t smem_u32(const void* p) {
    uint32_t a;
    asm("{ .reg .u64 t; cvta.to.shared.u64 t, %1; cvt.u32.u64 %0, t; }" : "=r"(a) : "l"(p));
    return a;
}
__device__ __forceinline__ void cp16(uint32_t s, const void* g) {
    asm volatile("cp.async.cg.shared.global [%0], [%1], 16;" :: "r"(s), "l"(g));
}
__device__ __forceinline__ void ldsm4(uint32_t a, uint32_t* r) {
    asm volatile("ldmatrix.sync.aligned.m8n8.x4.shared.b16 {%0,%1,%2,%3}, [%4];"
                 : "=r"(r[0]), "=r"(r[1]), "=r"(r[2]), "=r"(r[3]) : "r"(a));
}
__device__ __forceinline__ void ldsm4t(uint32_t a, uint32_t* r) {
    asm volatile("ldmatrix.sync.aligned.m8n8.x4.trans.shared.b16 {%0,%1,%2,%3}, [%4];"
                 : "=r"(r[0]), "=r"(r[1]), "=r"(r[2]), "=r"(r[3]) : "r"(a));
}
__device__ __forceinline__ void mma16816(float* d, const uint32_t* a, const uint32_t* b) {
    asm volatile(
        "mma.sync.aligned.m16n8k16.row.col.f32.bf16.bf16.f32 "
        "{%0,%1,%2,%3}, {%4,%5,%6,%7}, {%8,%9}, {%0,%1,%2,%3};"
        : "+f"(d[0]), "+f"(d[1]), "+f"(d[2]), "+f"(d[3])
        : "r"(a[0]), "r"(a[1]), "r"(a[2]), "r"(a[3]), "r"(b[0]), "r"(b[1]));
}
__device__ __forceinline__ uint32_t packbf2(float x, float y) {
    __nv_bfloat162 h = __floats2bfloat162_rn(x, y);
    return *reinterpret_cast<uint32_t*>(&h);
}

// ---------------------------------------------------------------------------
__global__ __launch_bounds__(256) void fsplit(
    const float* __restrict__ X, __nv_bfloat16* __restrict__ H,
    __nv_bfloat16* __restrict__ L)
{
    const int i4 = blockIdx.x * blockDim.x + threadIdx.x;
    float4 v = reinterpret_cast<const float4*>(X)[i4];
    __nv_bfloat16 h0 = __float2bfloat16(v.x), h1 = __float2bfloat16(v.y);
    __nv_bfloat16 h2 = __float2bfloat16(v.z), h3 = __float2bfloat16(v.w);
    reinterpret_cast<__nv_bfloat162*>(H)[i4 * 2 + 0] = __halves2bfloat162(h0, h1);
    reinterpret_cast<__nv_bfloat162*>(H)[i4 * 2 + 1] = __halves2bfloat162(h2, h3);
    reinterpret_cast<__nv_bfloat162*>(L)[i4 * 2 + 0] = __floats2bfloat162_rn(
        v.x - __bfloat162float(h0), v.y - __bfloat162float(h1));
    reinterpret_cast<__nv_bfloat162*>(L)[i4 * 2 + 1] = __floats2bfloat162_rn(
        v.z - __bfloat162float(h2), v.w - __bfloat162float(h3));
}

__global__ void wsplit(const float* __restrict__ W0, const float* __restrict__ W1,
                       const float* __restrict__ W2, const float* __restrict__ W3,
                       __nv_bfloat16* __restrict__ ThB, __nv_bfloat16* __restrict__ TlB)
{
    __shared__ float t[32][33];
    const int z = blockIdx.z;
    const float* W = (z == 0) ? W0 : (z == 1) ? W1 : (z == 2) ? W2 : W3;
    __nv_bfloat16* Th = ThB + (size_t)z * DM * DM;
    __nv_bfloat16* Tl = TlB + (size_t)z * DM * DM;
    const int n0 = blockIdx.x * 32, k0 = blockIdx.y * 32;
    const int tx = threadIdx.x, ty = threadIdx.y;
    #pragma unroll
    for (int i = 0; i < 32; i += 8)
        t[ty + i][tx] = W[(size_t)(k0 + ty + i) * DM + n0 + tx];
    __syncthreads();
    #pragma unroll
    for (int i = 0; i < 32; i += 8) {
        float v = t[tx][ty + i];
        __nv_bfloat16 h = __float2bfloat16(v);
        Th[(size_t)(n0 + ty + i) * DM + k0 + tx] = h;
        Tl[(size_t)(n0 + ty + i) * DM + k0 + tx] = __float2bfloat16(v - __bfloat162float(h));
    }
}

// ---------------------------------------------------------------------------
// HMMA GEMM. CTA tile 128x256, warp tile 64x64, K-chunk 32, 3-stage cp.async.
// split=1: QKV fused via blockIdx.z, bf16 hi/lo head-scatter out; Q scaled 1/8.
// ---------------------------------------------------------------------------
#define SA_B      80
#define T_AH      0
#define T_AL      10240
#define T_BH      20480
#define T_BL      40960
#define STAGE_B   61440
#define GEMM_SMEM (3 * STAGE_B)
#define NCH       (DM / 32)

__global__ __launch_bounds__(256) void mma_gemm(
    const __nv_bfloat16* __restrict__ Ah, const __nv_bfloat16* __restrict__ Al,
    const __nv_bfloat16* __restrict__ WthB, const __nv_bfloat16* __restrict__ WtlB,
    const float* __restrict__ bias0, const float* __restrict__ bias1,
    const float* __restrict__ bias2,
    float* __restrict__ outF,
    __nv_bfloat16* oH0, __nv_bfloat16* oL0,
    __nv_bfloat16* oH1, __nv_bfloat16* oL1,
    __nv_bfloat16* oH2, __nv_bfloat16* oL2, int split)
{
    extern __shared__ char smem[];
    const uint32_t sb = smem_u32(smem);
    const int tid = threadIdx.x, wid = tid >> 5, lane = tid & 31;
    const int m0 = blockIdx.y << 7, n0 = blockIdx.x << 8;
    const int z = blockIdx.z;
    const __nv_bfloat16* Bh = WthB + (size_t)z * DM * DM;
    const __nv_bfloat16* Bl = WtlB + (size_t)z * DM * DM;
    const float* bias = (z == 0) ? bias0 : (z == 1) ? bias1 : bias2;
    __nv_bfloat16* oH = (z == 0) ? oH0 : (z == 1) ? oH1 : oH2;
    __nv_bfloat16* oL = (z == 0) ? oL0 : (z == 1) ? oL1 : oL2;
    const float oscale = (split && z == 0) ? 0.125f : 1.0f;   // fold 1/sqrt(64) into Q
    const int wm = wid & 1, wn = wid >> 1;

    float acc[4][8][4];
    #pragma unroll
    for (int i = 0; i < 4; i++)
        #pragma unroll
        for (int j = 0; j < 8; j++)
            #pragma unroll
            for (int e = 0; e < 4; e++) acc[i][j][e] = 0.f;

    const int lrow = tid >> 2, lseg = tid & 3;

    auto issue = [&](int c) {
        const uint32_t st = sb + (uint32_t)(c % 3) * STAGE_B;
        const int koff = c * 32;
        #pragma unroll
        for (int u = 0; u < 2; u++) {
            const int row = lrow + u * 64;
            const size_t ga = (size_t)(m0 + row) * DM + koff + lseg * 8;
            const uint32_t so = (uint32_t)(row * SA_B + lseg * 16);
            cp16(st + T_AH + so, Ah + ga);
            cp16(st + T_AL + so, Al + ga);
        }
        #pragma unroll
        for (int u = 0; u < 4; u++) {
            const int row = lrow + u * 64;
            const size_t gb = (size_t)(n0 + row) * DM + koff + lseg * 8;
            const uint32_t so = (uint32_t)(row * SA_B + lseg * 16);
            cp16(st + T_BH + so, Bh + gb);
            cp16(st + T_BL + so, Bl + gb);
        }
    };

    issue(0);
    asm volatile("cp.async.commit_group;");
    issue(1);
    asm volatile("cp.async.commit_group;");

    const int arow = lane & 15;
    const uint32_t akb = (uint32_t)((lane >> 4) << 4);
    const int bn = ((lane >> 4) << 3) + (lane & 7);
    const uint32_t bkb = (uint32_t)(((lane >> 3) & 1) << 4);

    for (int c = 0; c < NCH; c++) {
        if (c + 1 < NCH) { asm volatile("cp.async.wait_group 1;"); }
        else             { asm volatile("cp.async.wait_group 0;"); }
        __syncthreads();
        if (c + 2 < NCH) {
            issue(c + 2);
            asm volatile("cp.async.commit_group;");
        }

        const uint32_t st = sb + (uint32_t)(c % 3) * STAGE_B;
        #pragma unroll
        for (int ks = 0; ks < 2; ks++) {
            const uint32_t kb = (uint32_t)ks * 32;
            uint32_t ah[4][4], al[4][4];
            #pragma unroll
            for (int i = 0; i < 4; i++) {
                const uint32_t ra = (uint32_t)((wm * 64 + i * 16 + arow) * SA_B) + kb + akb;
                ldsm4(st + T_AH + ra, ah[i]);
                ldsm4(st + T_AL + ra, al[i]);
            }
            #pragma unroll
            for (int jp = 0; jp < 4; jp++) {
                const uint32_t rb = (uint32_t)((wn * 64 + jp * 16 + bn) * SA_B) + kb + bkb;
                uint32_t t[4], u4[4];
                ldsm4(st + T_BH + rb, t);
                ldsm4(st + T_BL + rb, u4);
                uint32_t b0[2] = {t[0], t[1]}, b1[2] = {t[2], t[3]};
                uint32_t c0[2] = {u4[0], u4[1]}, c1[2] = {u4[2], u4[3]};
                #pragma unroll
                for (int i = 0; i < 4; i++) {
                    mma16816(acc[i][2*jp],   ah[i], b0);
                    mma16816(acc[i][2*jp],   al[i], b0);
                    mma16816(acc[i][2*jp],   ah[i], c0);
                    mma16816(acc[i][2*jp+1], ah[i], b1);
                    mma16816(acc[i][2*jp+1], al[i], b1);
                    mma16816(acc[i][2*jp+1], ah[i], c1);
                }
            }
        }
        __syncthreads();
    }

    const int qr = lane >> 2, qc = (lane & 3) * 2;
    #pragma unroll
    for (int i = 0; i < 4; i++) {
        #pragma unroll
        for (int half = 0; half < 2; half++) {
            const int m = m0 + wm * 64 + i * 16 + qr + half * 8;
            const int bb = m >> 11, ss = m & 2047;
            #pragma unroll
            for (int j = 0; j < 8; j++) {
                const int n = n0 + wn * 64 + j * 8 + qc;
                const float vx = (acc[i][j][half * 2 + 0] + bias[n]) * oscale;
                const float vy = (acc[i][j][half * 2 + 1] + bias[n + 1]) * oscale;
                if (split) {
                    const int h = n >> 6, d = n & 63;
                    const size_t o = (((size_t)(bb * NH + h) * S_) + ss) * HD + d;
                    __nv_bfloat162 hv = __floats2bfloat162_rn(vx, vy);
                    __nv_bfloat162 lv = __floats2bfloat162_rn(
                        vx - __bfloat162float(hv.x), vy - __bfloat162float(hv.y));
                    *reinterpret_cast<__nv_bfloat162*>(&oH[o]) = hv;
                    *reinterpret_cast<__nv_bfloat162*>(&oL[o]) = lv;
                } else {
                    float2 v; v.x = vx; v.y = vy;
                    *reinterpret_cast<float2*>(&outF[(size_t)m * DM + n]) = v;
                }
            }
        }
    }
}

// ---------------------------------------------------------------------------
// HMMA flash attention. 128 q-rows/CTA, 64-key tiles, 2 CTAs/SM.
// Q fragments re-loaded from smem each k-step (register diet for occupancy).
// Q is pre-scaled by 1/8 in the projection epilogue.
// ---------------------------------------------------------------------------
#define ARS    144
#define AQH    0
#define AQL    (128 * ARS)
#define ASTG   (2 * 128 * ARS)
#define AKH    0
#define AKL    (64 * ARS)
#define AVH    (2 * 64 * ARS)
#define AVL    (3 * 64 * ARS)
#define STG_SZ (4 * 64 * ARS)
#define ATTN_SMEM (ASTG + 2 * STG_SZ)     // 110592

__global__ __launch_bounds__(256, 2) void attn_mma(
    const __nv_bfloat16* __restrict__ Qh_, const __nv_bfloat16* __restrict__ Ql_,
    const __nv_bfloat16* __restrict__ Kh_, const __nv_bfloat16* __restrict__ Kl_,
    const __nv_bfloat16* __restrict__ Vh_, const __nv_bfloat16* __restrict__ Vl_,
    __nv_bfloat16* __restrict__ Ch_, __nv_bfloat16* __restrict__ Cl_)
{
    extern __shared__ char smem[];
    const uint32_t sb = smem_u32(smem);
    const int tid = threadIdx.x, wid = tid >> 5, lane = tid & 31;
    const int bh = blockIdx.y, q0 = blockIdx.x << 7;
    const size_t hb = (size_t)bh * S_ * HD;

    #pragma unroll
    for (int u = 0; u < 4; u++) {
        const int s = tid + u * 256;
        const int row = s >> 3, seg = s & 7;
        const size_t g = hb + (size_t)(q0 + row) * HD + seg * 8;
        const uint32_t so = (uint32_t)(row * ARS + seg * 16);
        cp16(sb + AQH + so, Qh_ + g);
        cp16(sb + AQL + so, Ql_ + g);
    }

    auto issueKV = [&](int kt) {
        const uint32_t st = sb + ASTG + (uint32_t)(kt & 1) * STG_SZ;
        #pragma unroll
        for (int u = 0; u < 2; u++) {
            const int s = tid + u * 256;
            const int row = s >> 3, seg = s & 7;
            const size_t g = hb + (size_t)(kt * 64 + row) * HD + seg * 8;
            const uint32_t so = (uint32_t)(row * ARS + seg * 16);
            cp16(st + AKH + so, Kh_ + g);
            cp16(st + AKL + so, Kl_ + g);
            cp16(st + AVH + so, Vh_ + g);
            cp16(st + AVL + so, Vl_ + g);
        }
    };

    issueKV(0);
    asm volatile("cp.async.commit_group;");

    float O[8][4];
    #pragma unroll
    for (int j = 0; j < 8; j++)
        #pragma unroll
        for (int e = 0; e < 4; e++) O[j][e] = 0.f;
    float m0v = -1e30f, m1v = -1e30f, l0v = 0.f, l1v = 0.f;

    const int bn = ((lane >> 4) << 3) + (lane & 7);
    const uint32_t bkb = ((lane >> 3) & 1) << 4;
    const int vg = lane >> 3, vi = lane & 7;
    const uint32_t qbase = sb + (uint32_t)((wid * 16 + (lane & 15)) * ARS)
                         + (uint32_t)((lane >> 4) << 4);

    for (int kt = 0; kt < S_ / 64; kt++) {
        if (kt + 1 < S_ / 64) {
            issueKV(kt + 1);
            asm volatile("cp.async.commit_group;");
            asm volatile("cp.async.wait_group 1;");
        } else {
            asm volatile("cp.async.wait_group 0;");
        }
        __syncthreads();

        const uint32_t stg = sb + ASTG + (uint32_t)(kt & 1) * STG_SZ;

        // ---- scores (Q pre-scaled by 1/8) ----
        float sc[8][4];
        #pragma unroll
        for (int j = 0; j < 8; j++)
            #pragma unroll
            for (int e = 0; e < 4; e++) sc[j][e] = 0.f;

        #pragma unroll
        for (int ks = 0; ks < 4; ks++) {
            uint32_t qh[4], ql[4];
            ldsm4(qbase + AQH + ks * 32, qh);
            ldsm4(qbase + AQL + ks * 32, ql);
            #pragma unroll
            for (int jp = 0; jp < 4; jp++) {
                const uint32_t addr = stg + (uint32_t)((jp * 16 + bn) * ARS) + ks * 32 + bkb;
                uint32_t t[4], u[4];
                ldsm4(addr + AKH, t);
                ldsm4(addr + AKL, u);
                uint32_t b0[2] = {t[0], t[1]}, b1[2] = {t[2], t[3]};
                uint32_t c0[2] = {u[0], u[1]}, c1[2] = {u[2], u[3]};
                mma16816(sc[2*jp],   qh, b0);
                mma16816(sc[2*jp+1], qh, b1);
                mma16816(sc[2*jp],   ql, b0);
                mma16816(sc[2*jp+1], ql, b1);
                mma16816(sc[2*jp],   qh, c0);
                mma16816(sc[2*jp+1], qh, c1);
            }
        }

        // ---- online softmax (rows qr, qr+8) ----
        float t0 = -1e30f, t1 = -1e30f;
        #pragma unroll
        for (int j = 0; j < 8; j++) {
            t0 = fmaxf(t0, fmaxf(sc[j][0], sc[j][1]));
            t1 = fmaxf(t1, fmaxf(sc[j][2], sc[j][3]));
        }
        t0 = fmaxf(t0, __shfl_xor_sync(0xffffffffu, t0, 1));
        t0 = fmaxf(t0, __shfl_xor_sync(0xffffffffu, t0, 2));
        t1 = fmaxf(t1, __shfl_xor_sync(0xffffffffu, t1, 1));
        t1 = fmaxf(t1, __shfl_xor_sync(0xffffffffu, t1, 2));
        const float mn0 = fmaxf(m0v, t0), mn1 = fmaxf(m1v, t1);
        const float cr0 = __expf(m0v - mn0), cr1 = __expf(m1v - mn1);
        float s0 = 0.f, s1 = 0.f;
        #pragma unroll
        for (int j = 0; j < 8; j++) {
            sc[j][0] = __expf(sc[j][0] - mn0); s0 += sc[j][0];
            sc[j][1] = __expf(sc[j][1] - mn0); s0 += sc[j][1];
            sc[j][2] = __expf(sc[j][2] - mn1); s1 += sc[j][2];
            sc[j][3] = __expf(sc[j][3] - mn1); s1 += sc[j][3];
        }
        s0 += __shfl_xor_sync(0xffffffffu, s0, 1);
        s0 += __shfl_xor_sync(0xffffffffu, s0, 2);
        s1 += __shfl_xor_sync(0xffffffffu, s1, 1);
        s1 += __shfl_xor_sync(0xffffffffu, s1, 2);
        l0v = l0v * cr0 + s0;  m0v = mn0;
        l1v = l1v * cr1 + s1;  m1v = mn1;
        #pragma unroll
        for (int j = 0; j < 8; j++) {
            O[j][0] *= cr0; O[j][1] *= cr0;
            O[j][2] *= cr1; O[j][3] *= cr1;
        }

        // ---- P @ V ----
        #pragma unroll
        for (int ks = 0; ks < 4; ks++) {
            uint32_t ph[4], pl[4];
            {
                const float* p0 = sc[2*ks];
                const float* p1 = sc[2*ks+1];
                ph[0] = packbf2(p0[0], p0[1]);
                ph[1] = packbf2(p0[2], p0[3]);
                ph[2] = packbf2(p1[0], p1[1]);
                ph[3] = packbf2(p1[2], p1[3]);
                const __nv_bfloat162* h;
                h = reinterpret_cast<const __nv_bfloat162*>(&ph[0]);
                pl[0] = packbf2(p0[0] - __bfloat162float(h->x), p0[1] - __bfloat162float(h->y));
                h = reinterpret_cast<const __nv_bfloat162*>(&ph[1]);
                pl[1] = packbf2(p0[2] - __bfloat162float(h->x), p0[3] - __bfloat162float(h->y));
                h = reinterpret_cast<const __nv_bfloat162*>(&ph[2]);
                pl[2] = packbf2(p1[0] - __bfloat162float(h->x), p1[1] - __bfloat162float(h->y));
                h = reinterpret_cast<const __nv_bfloat162*>(&ph[3]);
                pl[3] = packbf2(p1[2] - __bfloat162float(h->x), p1[3] - __bfloat162float(h->y));
            }
            #pragma unroll
            for (int djp = 0; djp < 4; djp++) {
                const uint32_t vaddr = stg
                    + (uint32_t)((ks * 16 + (vg & 1) * 8 + vi) * ARS)
                    + (uint32_t)((djp * 16 + (vg >> 1) * 8) * 2);
                uint32_t t[4], u[4];
                ldsm4t(vaddr + AVH, t);
                ldsm4t(vaddr + AVL, u);
                uint32_t b0[2] = {t[0], t[1]}, b1[2] = {t[2], t[3]};
                uint32_t c0[2] = {u[0], u[1]}, c1[2] = {u[2], u[3]};
                mma16816(O[2*djp],   ph, b0);
                mma16816(O[2*djp+1], ph, b1);
                mma16816(O[2*djp],   pl, b0);
                mma16816(O[2*djp+1], pl, b1);
                mma16816(O[2*djp],   ph, c0);
                mma16816(O[2*djp+1], ph, c1);
            }
        }
        __syncthreads();
    }

    // ---- epilogue ----
    const int bb = bh / NH, hh = bh % NH;
    const int qr = lane >> 2, qc = (lane & 3) * 2;
    const float inv0 = 1.0f / l0v, inv1 = 1.0f / l1v;
    const int r0 = q0 + wid * 16 + qr;
    #pragma unroll
    for (int j = 0; j < 8; j++) {
        const int col = hh * HD + j * 8 + qc;
        {
            const size_t o = (size_t)(bb * S_ + r0) * DM + col;
            const float vx = O[j][0] * inv0, vy = O[j][1] * inv0;
            __nv_bfloat162 hv = __floats2bfloat162_rn(vx, vy);
            __nv_bfloat162 lv = __floats2bfloat162_rn(
                vx - __bfloat162float(hv.x), vy - __bfloat162float(hv.y));
            *reinterpret_cast<__nv_bfloat162*>(&Ch_[o]) = hv;
            *reinterpret_cast<__nv_bfloat162*>(&Cl_[o]) = lv;
        }
        {
            const size_t o = (size_t)(bb * S_ + r0 + 8) * DM + col;
            const float vx = O[j][2] * inv1, vy = O[j][3] * inv1;
            __nv_bfloat162 hv = __floats2bfloat162_rn(vx, vy);
            __nv_bfloat162 lv = __floats2bfloat162_rn(
                vx - __bfloat162float(hv.x), vy - __bfloat162float(hv.y));
            *reinterpret_cast<__nv_bfloat162*>(&Ch_[o]) = hv;
            *reinterpret_cast<__nv_bfloat162*>(&Cl_[o]) = lv;
        }
    }
}

// ---------------------------------------------------------------------------
extern "C" void kernel_launch(void* const* d_in, const int* in_sizes, int n_in,
                              void* d_out, int out_size)
{
    const float* x  = (const float*)d_in[0];
    const float* Wq = (const float*)d_in[1];
    const float* bq = (const float*)d_in[2];
    const float* Wk = (const float*)d_in[3];
    const float* bk = (const float*)d_in[4];
    const float* Wv = (const float*)d_in[5];
    const float* bv = (const float*)d_in[6];
    const float* Wo = (const float*)d_in[7];
    const float* bo = (const float*)d_in[8];

    __nv_bfloat16 *Qh, *Ql, *Kh, *Kl, *Vh, *Vl, *xh, *xl, *Ch, *Cl, *Wth, *Wtl;
    cudaGetSymbolAddress((void**)&Qh, g_Qh);
    cudaGetSymbolAddress((void**)&Ql, g_Ql);
    cudaGetSymbolAddress((void**)&Kh, g_Kh);
    cudaGetSymbolAddress((void**)&Kl, g_Kl);
    cudaGetSymbolAddress((void**)&Vh, g_Vh);
    cudaGetSymbolAddress((void**)&Vl, g_Vl);
    cudaGetSymbolAddress((void**)&xh, g_xh);
    cudaGetSymbolAddress((void**)&xl, g_xl);
    cudaGetSymbolAddress((void**)&Ch, g_Ch);
    cudaGetSymbolAddress((void**)&Cl, g_Cl);
    cudaGetSymbolAddress((void**)&Wth, g_Wth);
    cudaGetSymbolAddress((void**)&Wtl, g_Wtl);

    cudaFuncSetAttribute(mma_gemm, cudaFuncAttributeMaxDynamicSharedMemorySize, GEMM_SMEM);
    cudaFuncSetAttribute(attn_mma, cudaFuncAttributeMaxDynamicSharedMemorySize, ATTN_SMEM);

    fsplit<<<(MTOT * DM) / 4 / 256, 256>>>(x, xh, xl);
    wsplit<<<dim3(DM / 32, DM / 32, 4), dim3(32, 8)>>>(Wq, Wk, Wv, Wo, Wth, Wtl);

    mma_gemm<<<dim3(DM / 256, MTOT / 128, 3), 256, GEMM_SMEM>>>(
        xh, xl, Wth, Wtl, bq, bk, bv,
        nullptr, Qh, Ql, Kh, Kl, Vh, Vl, 1);

    attn_mma<<<dim3(S_ / 128, BH), 256, ATTN_SMEM>>>(Qh, Ql, Kh, Kl, Vh, Vl, Ch, Cl);

    mma_gemm<<<dim3(DM / 256, MTOT / 128, 1), 256, GEMM_SMEM>>>(
        Ch, Cl, Wth + 3 * DM * DM, Wtl + 3 * DM * DM, bo, bo, bo,
        (float*)d_out, nullptr, nullptr, nullptr, nullptr, nullptr, nullptr, 0);
}

// round 7
// speedup vs baseline: 1.4823x; 1.4823x over previous
#include <cuda_runtime.h>
#include <cuda_bf16.h>
#include <cstdint>

#define DM   768
#define NH   12
#define HD   64
#define B_   2
#define S_   2048
#define MTOT 4096
#define BH   (B_*NH)

// ---------------- scratch (__device__ globals) ------------------------------
__device__ __nv_bfloat16 g_Qh[BH * S_ * HD];
__device__ __nv_bfloat16 g_Ql[BH * S_ * HD];
__device__ __nv_bfloat16 g_Kh[BH * S_ * HD];
__device__ __nv_bfloat16 g_Kl[BH * S_ * HD];
__device__ __nv_bfloat16 g_Vh[BH * S_ * HD];
__device__ __nv_bfloat16 g_Vl[BH * S_ * HD];
__device__ __nv_bfloat16 g_xh[MTOT * DM];
__device__ __nv_bfloat16 g_xl[MTOT * DM];
__device__ __nv_bfloat16 g_Ch[MTOT * DM];
__device__ __nv_bfloat16 g_Cl[MTOT * DM];
__device__ __nv_bfloat16 g_Wth[4 * DM * DM];   // [N,K] hi
__device__ __nv_bfloat16 g_Wtl[4 * DM * DM];   // [N,K] lo

// ---------------- helpers ---------------------------------------------------
__device__ __forceinline__ uint32_t smem_u32(const void* p) {
    uint32_t a;
    asm("{ .reg .u64 t; cvta.to.shared.u64 t, %1; cvt.u32.u64 %0, t; }" : "=r"(a) : "l"(p));
    return a;
}
__device__ __forceinline__ void cp16(uint32_t s, const void* g) {
    asm volatile("cp.async.cg.shared.global [%0], [%1], 16;" :: "r"(s), "l"(g));
}
__device__ __forceinline__ void ldsm4(uint32_t a, uint32_t* r) {
    asm volatile("ldmatrix.sync.aligned.m8n8.x4.shared.b16 {%0,%1,%2,%3}, [%4];"
                 : "=r"(r[0]), "=r"(r[1]), "=r"(r[2]), "=r"(r[3]) : "r"(a));
}
__device__ __forceinline__ void ldsm4t(uint32_t a, uint32_t* r) {
    asm volatile("ldmatrix.sync.aligned.m8n8.x4.trans.shared.b16 {%0,%1,%2,%3}, [%4];"
                 : "=r"(r[0]), "=r"(r[1]), "=r"(r[2]), "=r"(r[3]) : "r"(a));
}
__device__ __forceinline__ void mma16816(float* d, const uint32_t* a, const uint32_t* b) {
    asm volatile(
        "mma.sync.aligned.m16n8k16.row.col.f32.bf16.bf16.f32 "
        "{%0,%1,%2,%3}, {%4,%5,%6,%7}, {%8,%9}, {%0,%1,%2,%3};"
        : "+f"(d[0]), "+f"(d[1]), "+f"(d[2]), "+f"(d[3])
        : "r"(a[0]), "r"(a[1]), "r"(a[2]), "r"(a[3]), "r"(b[0]), "r"(b[1]));
}
__device__ __forceinline__ uint32_t packbf2(float x, float y) {
    __nv_bfloat162 h = __floats2bfloat162_rn(x, y);
    return *reinterpret_cast<uint32_t*>(&h);
}

// ---------------------------------------------------------------------------
__global__ __launch_bounds__(256) void fsplit(
    const float* __restrict__ X, __nv_bfloat16* __restrict__ H,
    __nv_bfloat16* __restrict__ L)
{
    const int i4 = blockIdx.x * blockDim.x + threadIdx.x;
    float4 v = reinterpret_cast<const float4*>(X)[i4];
    __nv_bfloat16 h0 = __float2bfloat16(v.x), h1 = __float2bfloat16(v.y);
    __nv_bfloat16 h2 = __float2bfloat16(v.z), h3 = __float2bfloat16(v.w);
    reinterpret_cast<__nv_bfloat162*>(H)[i4 * 2 + 0] = __halves2bfloat162(h0, h1);
    reinterpret_cast<__nv_bfloat162*>(H)[i4 * 2 + 1] = __halves2bfloat162(h2, h3);
    reinterpret_cast<__nv_bfloat162*>(L)[i4 * 2 + 0] = __floats2bfloat162_rn(
        v.x - __bfloat162float(h0), v.y - __bfloat162float(h1));
    reinterpret_cast<__nv_bfloat162*>(L)[i4 * 2 + 1] = __floats2bfloat162_rn(
        v.z - __bfloat162float(h2), v.w - __bfloat162float(h3));
}

__global__ void wsplit(const float* __restrict__ W0, const float* __restrict__ W1,
                       const float* __restrict__ W2, const float* __restrict__ W3,
                       __nv_bfloat16* __restrict__ ThB, __nv_bfloat16* __restrict__ TlB)
{
    __shared__ float t[32][33];
    const int z = blockIdx.z;
    const float* W = (z == 0) ? W0 : (z == 1) ? W1 : (z == 2) ? W2 : W3;
    __nv_bfloat16* Th = ThB + (size_t)z * DM * DM;
    __nv_bfloat16* Tl = TlB + (size_t)z * DM * DM;
    const int n0 = blockIdx.x * 32, k0 = blockIdx.y * 32;
    const int tx = threadIdx.x, ty = threadIdx.y;
    #pragma unroll
    for (int i = 0; i < 32; i += 8)
        t[ty + i][tx] = W[(size_t)(k0 + ty + i) * DM + n0 + tx];
    __syncthreads();
    #pragma unroll
    for (int i = 0; i < 32; i += 8) {
        float v = t[tx][ty + i];
        __nv_bfloat16 h = __float2bfloat16(v);
        Th[(size_t)(n0 + ty + i) * DM + k0 + tx] = h;
        Tl[(size_t)(n0 + ty + i) * DM + k0 + tx] = __float2bfloat16(v - __bfloat162float(h));
    }
}

// ---------------------------------------------------------------------------
// HMMA GEMM. CTA tile 128x256, warp tile 64x64, K-chunk 32, 3-stage cp.async.
// split=1: QKV fused via blockIdx.z, bf16 hi/lo head-scatter out; Q scaled 1/8.
// ---------------------------------------------------------------------------
#define SA_B      80
#define T_AH      0
#define T_AL      10240
#define T_BH      20480
#define T_BL      40960
#define STAGE_B   61440
#define GEMM_SMEM (3 * STAGE_B)
#define NCH       (DM / 32)

__global__ __launch_bounds__(256) void mma_gemm(
    const __nv_bfloat16* __restrict__ Ah, const __nv_bfloat16* __restrict__ Al,
    const __nv_bfloat16* __restrict__ WthB, const __nv_bfloat16* __restrict__ WtlB,
    const float* __restrict__ bias0, const float* __restrict__ bias1,
    const float* __restrict__ bias2,
    float* __restrict__ outF,
    __nv_bfloat16* oH0, __nv_bfloat16* oL0,
    __nv_bfloat16* oH1, __nv_bfloat16* oL1,
    __nv_bfloat16* oH2, __nv_bfloat16* oL2, int split)
{
    extern __shared__ char smem[];
    const uint32_t sb = smem_u32(smem);
    const int tid = threadIdx.x, wid = tid >> 5, lane = tid & 31;
    const int m0 = blockIdx.y << 7, n0 = blockIdx.x << 8;
    const int z = blockIdx.z;
    const __nv_bfloat16* Bh = WthB + (size_t)z * DM * DM;
    const __nv_bfloat16* Bl = WtlB + (size_t)z * DM * DM;
    const float* bias = (z == 0) ? bias0 : (z == 1) ? bias1 : bias2;
    __nv_bfloat16* oH = (z == 0) ? oH0 : (z == 1) ? oH1 : oH2;
    __nv_bfloat16* oL = (z == 0) ? oL0 : (z == 1) ? oL1 : oL2;
    const float oscale = (split && z == 0) ? 0.125f : 1.0f;
    const int wm = wid & 1, wn = wid >> 1;

    float acc[4][8][4];
    #pragma unroll
    for (int i = 0; i < 4; i++)
        #pragma unroll
        for (int j = 0; j < 8; j++)
            #pragma unroll
            for (int e = 0; e < 4; e++) acc[i][j][e] = 0.f;

    const int lrow = tid >> 2, lseg = tid & 3;

    auto issue = [&](int c) {
        const uint32_t st = sb + (uint32_t)(c % 3) * STAGE_B;
        const int koff = c * 32;
        #pragma unroll
        for (int u = 0; u < 2; u++) {
            const int row = lrow + u * 64;
            const size_t ga = (size_t)(m0 + row) * DM + koff + lseg * 8;
            const uint32_t so = (uint32_t)(row * SA_B + lseg * 16);
            cp16(st + T_AH + so, Ah + ga);
            cp16(st + T_AL + so, Al + ga);
        }
        #pragma unroll
        for (int u = 0; u < 4; u++) {
            const int row = lrow + u * 64;
            const size_t gb = (size_t)(n0 + row) * DM + koff + lseg * 8;
            const uint32_t so = (uint32_t)(row * SA_B + lseg * 16);
            cp16(st + T_BH + so, Bh + gb);
            cp16(st + T_BL + so, Bl + gb);
        }
    };

    issue(0);
    asm volatile("cp.async.commit_group;");
    issue(1);
    asm volatile("cp.async.commit_group;");

    const int arow = lane & 15;
    const uint32_t akb = (uint32_t)((lane >> 4) << 4);
    const int bn = ((lane >> 4) << 3) + (lane & 7);
    const uint32_t bkb = (uint32_t)(((lane >> 3) & 1) << 4);

    for (int c = 0; c < NCH; c++) {
        if (c + 1 < NCH) { asm volatile("cp.async.wait_group 1;"); }
        else             { asm volatile("cp.async.wait_group 0;"); }
        __syncthreads();
        if (c + 2 < NCH) {
            issue(c + 2);
            asm volatile("cp.async.commit_group;");
        }

        const uint32_t st = sb + (uint32_t)(c % 3) * STAGE_B;
        #pragma unroll
        for (int ks = 0; ks < 2; ks++) {
            const uint32_t kb = (uint32_t)ks * 32;
            uint32_t ah[4][4], al[4][4];
            #pragma unroll
            for (int i = 0; i < 4; i++) {
                const uint32_t ra = (uint32_t)((wm * 64 + i * 16 + arow) * SA_B) + kb + akb;
                ldsm4(st + T_AH + ra, ah[i]);
                ldsm4(st + T_AL + ra, al[i]);
            }
            #pragma unroll
            for (int jp = 0; jp < 4; jp++) {
                const uint32_t rb = (uint32_t)((wn * 64 + jp * 16 + bn) * SA_B) + kb + bkb;
                uint32_t t[4], u4[4];
                ldsm4(st + T_BH + rb, t);
                ldsm4(st + T_BL + rb, u4);
                uint32_t b0[2] = {t[0], t[1]}, b1[2] = {t[2], t[3]};
                uint32_t c0[2] = {u4[0], u4[1]}, c1[2] = {u4[2], u4[3]};
                #pragma unroll
                for (int i = 0; i < 4; i++) {
                    mma16816(acc[i][2*jp],   ah[i], b0);
                    mma16816(acc[i][2*jp],   al[i], b0);
                    mma16816(acc[i][2*jp],   ah[i], c0);
                    mma16816(acc[i][2*jp+1], ah[i], b1);
                    mma16816(acc[i][2*jp+1], al[i], b1);
                    mma16816(acc[i][2*jp+1], ah[i], c1);
                }
            }
        }
        __syncthreads();
    }

    const int qr = lane >> 2, qc = (lane & 3) * 2;
    #pragma unroll
    for (int i = 0; i < 4; i++) {
        #pragma unroll
        for (int half = 0; half < 2; half++) {
            const int m = m0 + wm * 64 + i * 16 + qr + half * 8;
            const int bb = m >> 11, ss = m & 2047;
            #pragma unroll
            for (int j = 0; j < 8; j++) {
                const int n = n0 + wn * 64 + j * 8 + qc;
                const float vx = (acc[i][j][half * 2 + 0] + bias[n]) * oscale;
                const float vy = (acc[i][j][half * 2 + 1] + bias[n + 1]) * oscale;
                if (split) {
                    const int h = n >> 6, d = n & 63;
                    const size_t o = (((size_t)(bb * NH + h) * S_) + ss) * HD + d;
                    __nv_bfloat162 hv = __floats2bfloat162_rn(vx, vy);
                    __nv_bfloat162 lv = __floats2bfloat162_rn(
                        vx - __bfloat162float(hv.x), vy - __bfloat162float(hv.y));
                    *reinterpret_cast<__nv_bfloat162*>(&oH[o]) = hv;
                    *reinterpret_cast<__nv_bfloat162*>(&oL[o]) = lv;
                } else {
                    float2 v; v.x = vx; v.y = vy;
                    *reinterpret_cast<float2*>(&outF[(size_t)m * DM + n]) = v;
                }
            }
        }
    }
}

// ---------------------------------------------------------------------------
// HMMA flash attention. 64 q-rows/CTA, 128 threads (4 warps x 16 rows),
// 64-key tiles, 2 CTAs/SM (occupancy from smaller CTA, regs untouched).
// Q pre-scaled by 1/8 in projection epilogue; Q frags register-resident.
// ---------------------------------------------------------------------------
#define ARS    144
#define AQH    0
#define AQL    (64 * ARS)                // 9216
#define ASTG   (2 * 64 * ARS)            // 18432
#define AKH    0
#define AKL    (64 * ARS)
#define AVH    (2 * 64 * ARS)
#define AVL    (3 * 64 * ARS)
#define STG_SZ (4 * 64 * ARS)            // 36864
#define ATTN_SMEM (ASTG + 2 * STG_SZ)    // 92160

__global__ __launch_bounds__(128, 2) void attn_mma(
    const __nv_bfloat16* __restrict__ Qh_, const __nv_bfloat16* __restrict__ Ql_,
    const __nv_bfloat16* __restrict__ Kh_, const __nv_bfloat16* __restrict__ Kl_,
    const __nv_bfloat16* __restrict__ Vh_, const __nv_bfloat16* __restrict__ Vl_,
    __nv_bfloat16* __restrict__ Ch_, __nv_bfloat16* __restrict__ Cl_)
{
    extern __shared__ char smem[];
    const uint32_t sb = smem_u32(smem);
    const int tid = threadIdx.x, wid = tid >> 5, lane = tid & 31;
    const int bh = blockIdx.y, q0 = blockIdx.x << 6;
    const size_t hb = (size_t)bh * S_ * HD;

    // Q tile: 64 rows x 8 segs, 128 threads -> 4 per thread per array
    #pragma unroll
    for (int u = 0; u < 4; u++) {
        const int s = tid + u * 128;
        const int row = s >> 3, seg = s & 7;
        const size_t g = hb + (size_t)(q0 + row) * HD + seg * 8;
        const uint32_t so = (uint32_t)(row * ARS + seg * 16);
        cp16(sb + AQH + so, Qh_ + g);
        cp16(sb + AQL + so, Ql_ + g);
    }

    auto issueKV = [&](int kt) {
        const uint32_t st = sb + ASTG + (uint32_t)(kt & 1) * STG_SZ;
        #pragma unroll
        for (int u = 0; u < 4; u++) {
            const int s = tid + u * 128;
            const int row = s >> 3, seg = s & 7;
            const size_t g = hb + (size_t)(kt * 64 + row) * HD + seg * 8;
            const uint32_t so = (uint32_t)(row * ARS + seg * 16);
            cp16(st + AKH + so, Kh_ + g);
            cp16(st + AKL + so, Kl_ + g);
            cp16(st + AVH + so, Vh_ + g);
            cp16(st + AVL + so, Vl_ + g);
        }
    };

    issueKV(0);
    asm volatile("cp.async.commit_group;");

    float O[8][4];
    #pragma unroll
    for (int j = 0; j < 8; j++)
        #pragma unroll
        for (int e = 0; e < 4; e++) O[j][e] = 0.f;
    float m0v = -1e30f, m1v = -1e30f, l0v = 0.f, l1v = 0.f;
    uint32_t qh[4][4], ql[4][4];

    const int bn = ((lane >> 4) << 3) + (lane & 7);
    const uint32_t bkb = ((lane >> 3) & 1) << 4;
    const int vg = lane >> 3, vi = lane & 7;

    for (int kt = 0; kt < S_ / 64; kt++) {
        if (kt + 1 < S_ / 64) {
            issueKV(kt + 1);
            asm volatile("cp.async.commit_group;");
            asm volatile("cp.async.wait_group 1;");
        } else {
            asm volatile("cp.async.wait_group 0;");
        }
        __syncthreads();

        if (kt == 0) {
            #pragma unroll
            for (int ks = 0; ks < 4; ks++) {
                const uint32_t a = sb + (uint32_t)((wid * 16 + (lane & 15)) * ARS)
                                 + ((lane >> 4) << 4) + ks * 32;
                ldsm4(a + AQH, qh[ks]);
                ldsm4(a + AQL, ql[ks]);
            }
        }

        const uint32_t stg = sb + ASTG + (uint32_t)(kt & 1) * STG_SZ;

        // ---- scores (Q pre-scaled by 1/8) ----
        float sc[8][4];
        #pragma unroll
        for (int j = 0; j < 8; j++)
            #pragma unroll
            for (int e = 0; e < 4; e++) sc[j][e] = 0.f;

        #pragma unroll
        for (int jp = 0; jp < 4; jp++) {
            #pragma unroll
            for (int ks = 0; ks < 4; ks++) {
                const uint32_t addr = stg + (uint32_t)((jp * 16 + bn) * ARS) + ks * 32 + bkb;
                uint32_t t[4], u[4];
                ldsm4(addr + AKH, t);
                ldsm4(addr + AKL, u);
                uint32_t b0[2] = {t[0], t[1]}, b1[2] = {t[2], t[3]};
                uint32_t c0[2] = {u[0], u[1]}, c1[2] = {u[2], u[3]};
                mma16816(sc[2*jp],   qh[ks], b0);
                mma16816(sc[2*jp],   ql[ks], b0);
                mma16816(sc[2*jp],   qh[ks], c0);
                mma16816(sc[2*jp+1], qh[ks], b1);
                mma16816(sc[2*jp+1], ql[ks], b1);
                mma16816(sc[2*jp+1], qh[ks], c1);
            }
        }

        // ---- online softmax (rows qr, qr+8) ----
        float t0 = -1e30f, t1 = -1e30f;
        #pragma unroll
        for (int j = 0; j < 8; j++) {
            t0 = fmaxf(t0, fmaxf(sc[j][0], sc[j][1]));
            t1 = fmaxf(t1, fmaxf(sc[j][2], sc[j][3]));
        }
        t0 = fmaxf(t0, __shfl_xor_sync(0xffffffffu, t0, 1));
        t0 = fmaxf(t0, __shfl_xor_sync(0xffffffffu, t0, 2));
        t1 = fmaxf(t1, __shfl_xor_sync(0xffffffffu, t1, 1));
        t1 = fmaxf(t1, __shfl_xor_sync(0xffffffffu, t1, 2));
        const float mn0 = fmaxf(m0v, t0), mn1 = fmaxf(m1v, t1);
        const float cr0 = __expf(m0v - mn0), cr1 = __expf(m1v - mn1);
        float s0 = 0.f, s1 = 0.f;
        #pragma unroll
        for (int j = 0; j < 8; j++) {
            sc[j][0] = __expf(sc[j][0] - mn0); s0 += sc[j][0];
            sc[j][1] = __expf(sc[j][1] - mn0); s0 += sc[j][1];
            sc[j][2] = __expf(sc[j][2] - mn1); s1 += sc[j][2];
            sc[j][3] = __expf(sc[j][3] - mn1); s1 += sc[j][3];
        }
        s0 += __shfl_xor_sync(0xffffffffu, s0, 1);
        s0 += __shfl_xor_sync(0xffffffffu, s0, 2);
        s1 += __shfl_xor_sync(0xffffffffu, s1, 1);
        s1 += __shfl_xor_sync(0xffffffffu, s1, 2);
        l0v = l0v * cr0 + s0;  m0v = mn0;
        l1v = l1v * cr1 + s1;  m1v = mn1;
        #pragma unroll
        for (int j = 0; j < 8; j++) {
            O[j][0] *= cr0; O[j][1] *= cr0;
            O[j][2] *= cr1; O[j][3] *= cr1;
        }

        // ---- P @ V ----
        #pragma unroll
        for (int ks = 0; ks < 4; ks++) {
            uint32_t ph[4], pl[4];
            {
                const float* p0 = sc[2*ks];
                const float* p1 = sc[2*ks+1];
                ph[0] = packbf2(p0[0], p0[1]);
                ph[1] = packbf2(p0[2], p0[3]);
                ph[2] = packbf2(p1[0], p1[1]);
                ph[3] = packbf2(p1[2], p1[3]);
                const __nv_bfloat162* h;
                h = reinterpret_cast<const __nv_bfloat162*>(&ph[0]);
                pl[0] = packbf2(p0[0] - __bfloat162float(h->x), p0[1] - __bfloat162float(h->y));
                h = reinterpret_cast<const __nv_bfloat162*>(&ph[1]);
                pl[1] = packbf2(p0[2] - __bfloat162float(h->x), p0[3] - __bfloat162float(h->y));
                h = reinterpret_cast<const __nv_bfloat162*>(&ph[2]);
                pl[2] = packbf2(p1[0] - __bfloat162float(h->x), p1[1] - __bfloat162float(h->y));
                h = reinterpret_cast<const __nv_bfloat162*>(&ph[3]);
                pl[3] = packbf2(p1[2] - __bfloat162float(h->x), p1[3] - __bfloat162float(h->y));
            }
            #pragma unroll
            for (int djp = 0; djp < 4; djp++) {
                const uint32_t vaddr = stg
                    + (uint32_t)((ks * 16 + (vg & 1) * 8 + vi) * ARS)
                    + (uint32_t)((djp * 16 + (vg >> 1) * 8) * 2);
                uint32_t t[4], u[4];
                ldsm4t(vaddr + AVH, t);
                ldsm4t(vaddr + AVL, u);
                uint32_t b0[2] = {t[0], t[1]}, b1[2] = {t[2], t[3]};
                uint32_t c0[2] = {u[0], u[1]}, c1[2] = {u[2], u[3]};
                mma16816(O[2*djp],   ph, b0);
                mma16816(O[2*djp],   pl, b0);
                mma16816(O[2*djp],   ph, c0);
                mma16816(O[2*djp+1], ph, b1);
                mma16816(O[2*djp+1], pl, b1);
                mma16816(O[2*djp+1], ph, c1);
            }
        }
        __syncthreads();
    }

    // ---- epilogue ----
    const int bb = bh / NH, hh = bh % NH;
    const int qr = lane >> 2, qc = (lane & 3) * 2;
    const float inv0 = 1.0f / l0v, inv1 = 1.0f / l1v;
    const int r0 = q0 + wid * 16 + qr;
    #pragma unroll
    for (int j = 0; j < 8; j++) {
        const int col = hh * HD + j * 8 + qc;
        {
            const size_t o = (size_t)(bb * S_ + r0) * DM + col;
            const float vx = O[j][0] * inv0, vy = O[j][1] * inv0;
            __nv_bfloat162 hv = __floats2bfloat162_rn(vx, vy);
            __nv_bfloat162 lv = __floats2bfloat162_rn(
                vx - __bfloat162float(hv.x), vy - __bfloat162float(hv.y));
            *reinterpret_cast<__nv_bfloat162*>(&Ch_[o]) = hv;
            *reinterpret_cast<__nv_bfloat162*>(&Cl_[o]) = lv;
        }
        {
            const size_t o = (size_t)(bb * S_ + r0 + 8) * DM + col;
            const float vx = O[j][2] * inv1, vy = O[j][3] * inv1;
            __nv_bfloat162 hv = __floats2bfloat162_rn(vx, vy);
            __nv_bfloat162 lv = __floats2bfloat162_rn(
                vx - __bfloat162float(hv.x), vy - __bfloat162float(hv.y));
            *reinterpret_cast<__nv_bfloat162*>(&Ch_[o]) = hv;
            *reinterpret_cast<__nv_bfloat162*>(&Cl_[o]) = lv;
        }
    }
}

// ---------------------------------------------------------------------------
extern "C" void kernel_launch(void* const* d_in, const int* in_sizes, int n_in,
                              void* d_out, int out_size)
{
    const float* x  = (const float*)d_in[0];
    const float* Wq = (const float*)d_in[1];
    const float* bq = (const float*)d_in[2];
    const float* Wk = (const float*)d_in[3];
    const float* bk = (const float*)d_in[4];
    const float* Wv = (const float*)d_in[5];
    const float* bv = (const float*)d_in[6];
    const float* Wo = (const float*)d_in[7];
    const float* bo = (const float*)d_in[8];

    __nv_bfloat16 *Qh, *Ql, *Kh, *Kl, *Vh, *Vl, *xh, *xl, *Ch, *Cl, *Wth, *Wtl;
    cudaGetSymbolAddress((void**)&Qh, g_Qh);
    cudaGetSymbolAddress((void**)&Ql, g_Ql);
    cudaGetSymbolAddress((void**)&Kh, g_Kh);
    cudaGetSymbolAddress((void**)&Kl, g_Kl);
    cudaGetSymbolAddress((void**)&Vh, g_Vh);
    cudaGetSymbolAddress((void**)&Vl, g_Vl);
    cudaGetSymbolAddress((void**)&xh, g_xh);
    cudaGetSymbolAddress((void**)&xl, g_xl);
    cudaGetSymbolAddress((void**)&Ch, g_Ch);
    cudaGetSymbolAddress((void**)&Cl, g_Cl);
    cudaGetSymbolAddress((void**)&Wth, g_Wth);
    cudaGetSymbolAddress((void**)&Wtl, g_Wtl);

    cudaFuncSetAttribute(mma_gemm, cudaFuncAttributeMaxDynamicSharedMemorySize, GEMM_SMEM);
    cudaFuncSetAttribute(attn_mma, cudaFuncAttributeMaxDynamicSharedMemorySize, ATTN_SMEM);

    fsplit<<<(MTOT * DM) / 4 / 256, 256>>>(x, xh, xl);
    wsplit<<<dim3(DM / 32, DM / 32, 4), dim3(32, 8)>>>(Wq, Wk, Wv, Wo, Wth, Wtl);

    mma_gemm<<<dim3(DM / 256, MTOT / 128, 3), 256, GEMM_SMEM>>>(
        xh, xl, Wth, Wtl, bq, bk, bv,
        nullptr, Qh, Ql, Kh, Kl, Vh, Vl, 1);

    attn_mma<<<dim3(S_ / 64, BH), 128, ATTN_SMEM>>>(Qh, Ql, Kh, Kl, Vh, Vl, Ch, Cl);

    mma_gemm<<<dim3(DM / 256, MTOT / 128, 1), 256, GEMM_SMEM>>>(
        Ch, Cl, Wth + 3 * DM * DM, Wtl + 3 * DM * DM, bo, bo, bo,
        (float*)d_out, nullptr, nullptr, nullptr, nullptr, nullptr, nullptr, 0);
}